// round 14
// baseline (speedup 1.0000x reference)
#include <cuda_runtime.h>
#include <cstdint>
#include <math.h>

typedef unsigned long long u64;
typedef unsigned int u32;

#define B_IMG  4
#define N_ANCH 76725
#define N_CLS  80
#define ROW_F  84            // 80 classes + 4 box regressors
#define KC     512           // K_CAND
#define CAP    2048
#define MAXPC  100
#define THRESH 2.30f
#define CITER  4             // float4s per thread in collect
#define NSH    4             // counter shards per task
#define CAP_SH 512           // candidate slots per shard (4*512 = CAP)
#define PADU   32            // u32 per counter (128B line padding)

// ----------------------------- global scratch -------------------------------
__device__ u32    g_cntp[B_IMG * N_CLS * NSH * PADU];        // padded counters
__device__ u64    g_cand[(size_t)B_IMG * N_CLS * NSH * CAP_SH];
__device__ float  g_CS[B_IMG * N_CLS * MAXPC];
__device__ float4 g_CB[B_IMG * N_CLS * MAXPC];
__device__ int    g_done[B_IMG];                             // last-CTA counters

// --------------------- XLA-exact sigmoid (logistic lowering) ----------------
__device__ __forceinline__ float xla_sigmoid(float x) {
    float hx = __fmul_rn(0.5f, x);
    float t;
    if (fabsf(hx) < 0.0004f) {
        t = hx;
    } else {
        float xc = fmaxf(fminf(hx, 7.99881172180175781f), -7.99881172180175781f);
        float x2 = __fmul_rn(xc, xc);
        float p = fmaf(x2, -2.76076847742355e-16f, 2.00018790482477e-13f);
        p = fmaf(x2, p, -8.60467152213735e-11f);
        p = fmaf(x2, p,  5.12229709037114e-08f);
        p = fmaf(x2, p,  1.48572235717979e-05f);
        p = fmaf(x2, p,  6.37261928875436e-04f);
        p = fmaf(x2, p,  4.89352455891786e-03f);
        p = __fmul_rn(xc, p);
        float q = fmaf(x2, 1.19825839466702e-06f, 1.18534705686654e-04f);
        q = fmaf(x2, q, 2.26843463243900e-03f);
        q = fmaf(x2, q, 4.89352518554385e-03f);
        t = __fdiv_rn(p, q);
    }
    return fmaf(0.5f, t, 0.5f);
}

// ----------------------------- control block --------------------------------
struct Ctl {
    int n, fb;
    u32 Bb, bc, Tb;
    int ngt;
    int tie, need, cnt, tcnt;
    int kept, m;
};

// ---- parallel "find rank-K bin from the top" over hist[nb] ------------------
__device__ __forceinline__ void find_bin_parallel(
    const u32* hist, int nb, int K, int ngt_in, Ctl* ct, u32* warpTot)
{
    const int tid = threadIdx.x;
    int g = nb >> 9;
    if (g < 1) g = 1;
    int hi = nb - 1 - tid * g;
    u32 tsum = 0;
#pragma unroll 4
    for (int e = 0; e < g; e++) {
        int bb = hi - e;
        if (bb >= 0) tsum += hist[bb];
    }
    u32 ln = tid & 31, wp = tid >> 5;
    u32 v = tsum;
#pragma unroll
    for (int off = 1; off < 32; off <<= 1) {
        u32 nv = __shfl_up_sync(0xFFFFFFFFu, v, off);
        if (ln >= off) v += nv;
    }
    if (ln == 31) warpTot[wp] = v;
    __syncthreads();
    if (wp == 0) {
        u32 w = (ln < 16) ? warpTot[ln] : 0;
#pragma unroll
        for (int off = 1; off < 16; off <<= 1) {
            u32 nv = __shfl_up_sync(0xFFFFFFFFu, w, off);
            if (ln >= off) w += nv;
        }
        if (ln < 16) warpTot[ln] = w;
    }
    __syncthreads();
    u32 excl = (v - tsum) + (wp ? warpTot[wp - 1] : 0u);
    u32 cum = (u32)ngt_in + excl;
#pragma unroll 4
    for (int e = 0; e < g; e++) {
        int bb = hi - e;
        if (bb < 0) break;
        u32 c = hist[bb];
        if ((int)cum < K && (int)(cum + c) >= K) {
            ct->Bb = (u32)bb; ct->bc = c; ct->ngt = (int)cum;
        }
        cum += c;
    }
    __syncthreads();
}

// ---- warp-0 bitonic sort of 64 u64 (2 per lane), descending, zero barriers -
__device__ __forceinline__ void warp64_sort_desc(u64& a0, u64& a1, int lane) {
#pragma unroll
    for (int k = 2; k <= 64; k <<= 1) {
        if (k == 64) { if (a0 < a1) { u64 t = a0; a0 = a1; a1 = t; } }
#pragma unroll
        for (int j = ((k >> 1) > 16 ? 16 : (k >> 1)); j >= 1; j >>= 1) {
            bool lower = (lane & j) == 0;
            bool d0 = (lane & k) == 0;
            bool d1 = ((lane + 32) & k) == 0;
            u64 p0 = __shfl_xor_sync(0xFFFFFFFFu, a0, j);
            u64 p1 = __shfl_xor_sync(0xFFFFFFFFu, a1, j);
            a0 = ((lower == d0) == (a0 >= p0)) ? a0 : p0;
            a1 = ((lower == d1) == (a1 >= p1)) ? a1 : p1;
        }
    }
}

// ---- hybrid shfl/smem bitonic sort of 512 u64, descending -------------------
__device__ __forceinline__ void sort512_desc(u64* arr) {
    const int tid = threadIdx.x;
    u64 v = arr[tid];
#pragma unroll
    for (int k = 2; k <= 512; k <<= 1) {
        bool desc = (tid & k) == 0;          // k=512 -> always true
        for (int j = k >> 1; j >= 32; j >>= 1) {
            __syncthreads();
            arr[tid] = v;
            __syncthreads();
            u64 pv = arr[tid ^ j];
            bool lower = (tid & j) == 0;
            v = ((lower == desc) == (v >= pv)) ? v : pv;
        }
#pragma unroll
        for (int j = ((k >> 1) > 16 ? 16 : (k >> 1)); j >= 1; j >>= 1) {
            u64 pv = __shfl_xor_sync(0xFFFFFFFFu, v, j);
            bool lower = (tid & j) == 0;
            v = ((lower == desc) == (v >= pv)) ? v : pv;
        }
    }
    __syncthreads();
    arr[tid] = v;
    __syncthreads();
}

// ------------- kernel 1: batched scan + fast-reject + candidate push ---------
__global__ void __launch_bounds__(256)
collect_kernel(const float* __restrict__ pred) {
    const int TOT = B_IMG * N_ANCH * 21;             // float4 count
    int base = blockIdx.x * (256 * CITER) + threadIdx.x;

    float4 v[CITER];
#pragma unroll
    for (int k = 0; k < CITER; k++) {
        int idx = base + k * 256;
        if (idx < TOT)
            v[k] = reinterpret_cast<const float4*>(pred)[idx];
    }

#pragma unroll
    for (int k = 0; k < CITER; k++) {
        int idx = base + k * 256;
        if (idx >= TOT) continue;
        float4 w = v[k];
        float m = fmaxf(fmaxf(w.x, w.y), fmaxf(w.z, w.w));
        if (m <= THRESH) continue;                    // fast reject (~95.8%)
        int b = idx / (N_ANCH * 21);
        int r = idx - b * (N_ANCH * 21);
        int a = r / 21;
        int q = r - a * 21;
        if (q == 20) continue;                        // box-regressor block
        int c0 = q * 4;
        int sh = a & (NSH - 1);
        u32 la = 0xFFFFFFFFu - (u32)a;
        float vals[4] = {w.x, w.y, w.z, w.w};
#pragma unroll
        for (int e = 0; e < 4; e++) {
            float x = vals[e];
            if (x > THRESH) {
                int slot = (b * N_CLS + c0 + e) * NSH + sh;
                u32 pos = atomicAdd(&g_cntp[slot * PADU], 1u);
                if (pos < CAP_SH) {
                    float s = xla_sigmoid(x);
                    g_cand[(size_t)slot * CAP_SH + pos] =
                        ((u64)__float_as_uint(s) << 32) | la;
                }
            }
        }
    }
}

// ------- kernel 2: per-(b,c) top-512 + NMS + top-100 + fused combine --------
struct NmsArrs {
    float4 box[KC];          // 8 KB
    float  area[KC];         // 2 KB
    float  score[KC];        // 2 KB
    u32    mask[128][16];    // 8 KB
    u32    rowAny[128];      // 0.5 KB
};
union BufU {
    u64     buf[CAP];                // 16 KB (candidate phase)
    NmsArrs nm;                      // 20.5 KB (NMS phase)
    float   Ssm[N_CLS * MAXPC];      // 31.25 KB (fused combine phase)
};

__global__ void __launch_bounds__(512)
nms_kernel(const float* __restrict__ pred, float* __restrict__ out) {
    __shared__ BufU u;
    __shared__ u64 key512[KC];       // 4 KB (also combine's sort buffer)
    __shared__ u32 hist[2048];       // 8 KB
    __shared__ u64 tiebuf[64];
    __shared__ u32 keepbm[16];
    __shared__ u32 validbm[16];
    __shared__ u32 warpTot[16];
    __shared__ int keepIdx[MAXPC];
    __shared__ int shCnt[NSH], shOff[NSH];
    __shared__ float awTab[45], ahTab[45];
    __shared__ int selDone, isLast, validCnt;
    __shared__ Ctl ct;

    const int tid  = threadIdx.x;
    const int lane = tid & 31;
    const int wrp  = tid >> 5;
    const int task = blockIdx.x;
    const int b = task / N_CLS, c = task % N_CLS;

    // ---- anchor dims table: 45 (lvl3,k) pairs, same double math as numpy ----
    if (tid < 45) {
        int lvl3 = tid / 9, k = tid % 9;
        double side = (double)(1 << (lvl3 + 5));      // 2^(level+2), level=lvl3+3
        double area = side * side;
        const double ratios[3] = {0.5, 1.0, 2.0};
        const double scales[3] = {1.0, 1.2599210498948732, 1.5874010519681994};
        double r = ratios[k / 3], s = scales[k % 3];
        double ahd = sqrt(area / r);
        double awd = area / ahd;
        awTab[tid] = (float)(s * awd);
        ahTab[tid] = (float)(s * ahd);
    }

    if (tid < NSH)
        shCnt[tid] = (int)g_cntp[(task * NSH + tid) * PADU];
    __syncthreads();
    if (tid == 0) {
        int n0 = 0, bad = 0, off = 0;
        for (int s = 0; s < NSH; s++) {
            shOff[s] = off;
            int cs = shCnt[s];
            if (cs > CAP_SH) bad = 1;
            n0 += cs; off += cs;
        }
        ct.n = n0;
        ct.fb = (bad || n0 < KC || n0 > CAP) ? 1 : 0;
        ct.cnt = 0; ct.tcnt = 0; ct.kept = 0; ct.tie = 0;
        selDone = 0;
    }
    __syncthreads();
    const int fb = ct.fb;

    if (!fb) {
        // normal path: concatenate shard segments (order-free set)
#pragma unroll
        for (int s = 0; s < NSH; s++) {
            int cs = shCnt[s], off = shOff[s];
            const u64* src = g_cand + (size_t)(task * NSH + s) * CAP_SH;
            for (int i = tid; i < cs; i += 512)
                u.buf[off + i] = src[i];
        }
        __syncthreads();
    } else {
        // ---------- fallback: exact radix select on full column ----------
        const float* colb = pred + (size_t)b * N_ANCH * ROW_F + c;
        const int shifts[3] = {20, 9, 0};
        const int widths[3] = {11, 11, 9};
        u32 prefix = 0; int ngt = 0;
        int found = 0;
        for (int lvl = 0; lvl < 3 && !found; lvl++) {
            int nb = 1 << widths[lvl];
            for (int i = tid; i < nb; i += 512) hist[i] = 0;
            __syncthreads();
            int sh = shifts[lvl]; u32 bm = (u32)(nb - 1); int psh = sh + widths[lvl];
            for (int a = tid; a < N_ANCH; a += 512) {
                float s = xla_sigmoid(colb[(size_t)a * ROW_F]);
                u32 kb = __float_as_uint(s);
                if ((kb >> psh) == prefix) atomicAdd(&hist[(kb >> sh) & bm], 1);
            }
            __syncthreads();
            find_bin_parallel(hist, nb, KC, ngt, &ct, warpTot);
            u32 Bb = ct.Bb; int cum = ct.ngt; u32 bc = ct.bc;
            if (cum + (int)bc <= CAP) {
                if (tid == 0) ct.Tb = ((prefix << widths[lvl]) | Bb) << sh;
                found = 1;
            } else if (lvl == 2) {
                if (tid == 0) {
                    ct.tie = 1;
                    ct.Tb = (prefix << 9) | Bb;
                    ct.need = KC - cum;
                }
                found = 1;
            } else {
                prefix = (prefix << widths[lvl]) | Bb;
                ngt = cum;
            }
            __syncthreads();
        }
        int tie = ct.tie; u32 Tb = ct.Tb;
        for (int a = tid; a < N_ANCH; a += 512) {
            float s = xla_sigmoid(colb[(size_t)a * ROW_F]);
            u32 kb = __float_as_uint(s);
            bool take = tie ? (kb > Tb) : (kb >= Tb);
            if (take) {
                int pos = atomicAdd(&ct.cnt, 1);
                u.buf[pos] = ((u64)kb << 32) | (0xFFFFFFFFu - (u32)a);
            }
        }
        __syncthreads();
        if (tid == 0 && tie) {
            int base = ct.cnt, got = 0, need = ct.need;
            for (int a = 0; a < N_ANCH && got < need; a++) {
                float s = xla_sigmoid(colb[(size_t)a * ROW_F]);
                if (__float_as_uint(s) == Tb) {
                    u.buf[base + got] = ((u64)Tb << 32) | (0xFFFFFFFFu - (u32)a);
                    got++;
                }
            }
            ct.cnt = base + got;
        }
        __syncthreads();
        if (tid == 0) { ct.n = ct.cnt; ct.cnt = 0; ct.tcnt = 0; }
        __syncthreads();
    }

    // ---------- exact top-512 SET selection into key512 ----------
    const int n = ct.n;                      // in [512, 2048]

    if (!fb) {
        // FAST single-level: keys are sigmoid(x>2.3) in (0.908, 1.0), so
        // key>>23 == 0x7E constant => bin=(key>>12)&0x7FF is monotone.
        if (tid == 0) { ct.cnt = 0; ct.tcnt = 0; }
        for (int i = tid; i < 2048; i += 512) hist[i] = 0;
        __syncthreads();
        for (int i = tid; i < n; i += 512) {
            u32 hk = (u32)(u.buf[i] >> 32);
            atomicAdd(&hist[(hk >> 12) & 0x7FF], 1);
        }
        __syncthreads();
        find_bin_parallel(hist, 2048, KC, 0, &ct, warpTot);
        u32 Bb = ct.Bb, bc = ct.bc; int ngt = ct.ngt;
        int need = KC - ngt;
        u32 thr    = (0x3F000u | Bb) << 12;
        u32 thrTop = ((0x3F000u | Bb) + 1u) << 12;
        if ((int)bc == need) {
            for (int i = tid; i < n; i += 512) {
                u64 e = u.buf[i];
                if ((u32)(e >> 32) >= thr) {
                    int p = atomicAdd(&ct.cnt, 1);
                    key512[p] = e;
                }
            }
            if (tid == 0) selDone = 1;
            __syncthreads();
        } else if (bc <= 64) {
            for (int i = tid; i < n; i += 512) {
                u64 e = u.buf[i];
                u32 hk = (u32)(e >> 32);
                if (hk >= thrTop) {
                    int p = atomicAdd(&ct.cnt, 1);
                    key512[p] = e;
                } else if (hk >= thr) {
                    int p = atomicAdd(&ct.tcnt, 1);
                    tiebuf[p] = e;
                }
            }
            __syncthreads();
            if (wrp == 0) {
                int bcv = ct.tcnt;
                u64 a0 = (lane < bcv) ? tiebuf[lane] : 0ull;
                u64 a1 = (lane + 32 < bcv) ? tiebuf[lane + 32] : 0ull;
                warp64_sort_desc(a0, a1, lane);
                tiebuf[lane] = a0; tiebuf[lane + 32] = a1;
            }
            __syncthreads();
            if (tid < need) key512[ngt + tid] = tiebuf[tid];
            if (tid == 0) selDone = 1;
            __syncthreads();
        } else {
            __syncthreads();                 // fall through to generic
        }
    }

    if (!selDone) {
        // ---------- generic 3-level select (exact for arbitrary keys) -------
        if (tid == 0) { ct.cnt = 0; ct.tcnt = 0; }
        __syncthreads();
        const int shiftsS[3] = {21, 10, 0};
        const int widthsS[3] = {11, 11, 10};
        u32 prefix = 0; int ngt = 0;
        int state = 0;                       // 1=whole-bin, 2=tie-sort, 3=bail
        u32 TkeyBin = 0; int sh_fin = 0; int need = 0;
        for (int lvl = 0; lvl < 3 && state == 0; lvl++) {
            int nb = 1 << widthsS[lvl];
            for (int i = tid; i < nb; i += 512) hist[i] = 0;
            __syncthreads();
            int sh = shiftsS[lvl]; u32 bm = (u32)(nb - 1); int psh = sh + widthsS[lvl];
            for (int i = tid; i < n; i += 512) {
                u32 hk = (u32)(u.buf[i] >> 32);
                if (lvl == 0 || (hk >> psh) == prefix)
                    atomicAdd(&hist[(hk >> sh) & bm], 1);
            }
            __syncthreads();
            find_bin_parallel(hist, nb, KC, ngt, &ct, warpTot);
            u32 Bb = ct.Bb; u32 bc = ct.bc; int ngt2 = ct.ngt;
            int nd = KC - ngt2;
            if ((int)bc == nd) {
                state = 1; TkeyBin = (prefix << widthsS[lvl]) | Bb; sh_fin = sh; ngt = ngt2;
            } else if (bc <= 64) {
                state = 2; TkeyBin = (prefix << widthsS[lvl]) | Bb; sh_fin = sh;
                ngt = ngt2; need = nd;
            } else if (lvl < 2) {
                prefix = (prefix << widthsS[lvl]) | Bb; ngt = ngt2;
            } else {
                state = 3; TkeyBin = (prefix << widthsS[lvl]) | Bb; sh_fin = sh; ngt = ngt2;
            }
            __syncthreads();
        }

        u64 Tkey   = ((u64)TkeyBin) << sh_fin;
        u64 binTop = ((u64)TkeyBin + 1) << sh_fin;

        if (state == 1) {
            for (int i = tid; i < n; i += 512) {
                u64 e = u.buf[i];
                if ((u64)(u32)(e >> 32) >= Tkey) {
                    int p = atomicAdd(&ct.cnt, 1);
                    key512[p] = e;
                }
            }
            __syncthreads();
        } else if (state == 2) {
            for (int i = tid; i < n; i += 512) {
                u64 e = u.buf[i];
                u64 hk = (u32)(e >> 32);
                if (hk >= binTop) {
                    int p = atomicAdd(&ct.cnt, 1);
                    key512[p] = e;
                } else if (hk >= Tkey) {
                    int p = atomicAdd(&ct.tcnt, 1);
                    tiebuf[p] = e;
                }
            }
            __syncthreads();
            if (wrp == 0) {
                int bcv = ct.tcnt;
                u64 a0 = (lane < bcv) ? tiebuf[lane] : 0ull;
                u64 a1 = (lane + 32 < bcv) ? tiebuf[lane + 32] : 0ull;
                warp64_sort_desc(a0, a1, lane);
                tiebuf[lane] = a0; tiebuf[lane + 32] = a1;
            }
            __syncthreads();
            if (tid < need) key512[ngt + tid] = tiebuf[tid];
            __syncthreads();
        } else {
            // bail: >64 identical high-keys at exact-key level (never for real data)
            for (int i = tid; i < n; i += 512) {
                u64 e = u.buf[i];
                if ((u64)(u32)(e >> 32) >= binTop) {
                    int p = atomicAdd(&ct.cnt, 1);
                    key512[p] = e;
                }
            }
            __syncthreads();
            if (tid == 0) {
                int base = ct.cnt, got = 0, needB = KC - base;
                u64 last = 0xFFFFFFFFFFFFFFFFull;
                while (got < needB) {
                    u64 best = 0;
                    for (int i = 0; i < n; i++) {
                        u64 e = u.buf[i];
                        if ((u32)(e >> 32) == TkeyBin && e < last && e > best) best = e;
                    }
                    key512[base + got] = best; got++; last = best;
                }
            }
            __syncthreads();
        }
    }
    sort512_desc(key512);

    // ---------- decode boxes (u.buf dead -> u.nm live) ----------
    bool myValid;
    {
        u64 e = key512[tid];
        u32 lo = (u32)e;
        int a = (int)(0xFFFFFFFFu - lo);
        float s = __uint_as_float((u32)(e >> 32));
        float4 p = reinterpret_cast<const float4*>(pred)[(size_t)(b * N_ANCH + a) * 21 + 20];
        int base, fw, stride, lvl3;
        if      (a < 57600) { base = 0;     fw = 80; stride = 8;   lvl3 = 0; }
        else if (a < 72000) { base = 57600; fw = 40; stride = 16;  lvl3 = 1; }
        else if (a < 75600) { base = 72000; fw = 20; stride = 32;  lvl3 = 2; }
        else if (a < 76500) { base = 75600; fw = 10; stride = 64;  lvl3 = 3; }
        else                { base = 76500; fw = 5;  stride = 128; lvl3 = 4; }
        int local = a - base;
        int k    = local % 9;
        int cell = local / 9;
        int ix = cell % fw;
        int iy = cell / fw;
        float acx = __fmul_rn(__fadd_rn((float)ix, 0.5f), (float)stride);
        float acy = __fmul_rn(__fadd_rn((float)iy, 0.5f), (float)stride);
        float aw = awTab[lvl3 * 9 + k];
        float ah = ahTab[lvl3 * 9 + k];
        float cx = fmaf(__fmul_rn(p.x, 0.1f), aw, acx);
        float cy = fmaf(__fmul_rn(p.y, 0.1f), ah, acy);
        float w  = __fmul_rn(expf(__fmul_rn(p.z, 0.2f)), aw);
        float h  = __fmul_rn(expf(__fmul_rn(p.w, 0.2f)), ah);
        u.nm.box[tid]  = make_float4(cx, cy, w, h);
        u.nm.area[tid] = __fmul_rn(fmaxf(__fsub_rn(w, cx), 0.0f),
                                   fmaxf(__fsub_rn(h, cy), 0.0f));
        u.nm.score[tid] = s;
        myValid = (w > cx) && (h > cy);
        unsigned bal = __ballot_sync(0xFFFFFFFFu, s > 0.05f);
        if (lane == 0) keepbm[wrp] = bal;
        unsigned vb = __ballot_sync(0xFFFFFFFFu, myValid);
        if (lane == 0) validbm[wrp] = vb;
    }
    __syncthreads();

    // ---------- greedy NMS: mask chunks + warp-cooperative sweep ----------
    float4 bc_ = u.nm.box[tid];
    float  ac_ = u.nm.area[tid];
    u32 kb = 0;
    if (wrp == 0 && lane < 16) kb = keepbm[lane];

    for (int r0 = 0; r0 < KC; r0 += 128) {
        for (int it = 0; it < 128; it++) {
            int row = r0 + it;
            bool rowValid = (validbm[row >> 5] >> (row & 31)) & 1u;   // uniform
            if (!rowValid) {
                if (lane == 0) u.nm.mask[it][wrp] = 0;
                continue;
            }
            float4 br = u.nm.box[row];
            float  ar = u.nm.area[row];
            bool sup = false;
            if (myValid && tid > row) {
                float ih = fmaxf(__fsub_rn(fminf(br.z, bc_.z), fmaxf(br.x, bc_.x)), 0.0f);
                float iw = fmaxf(__fsub_rn(fminf(br.w, bc_.w), fmaxf(br.y, bc_.y)), 0.0f);
                float inter = __fmul_rn(ih, iw);
                if (inter > 0.0f) {
                    float uni = __fsub_rn(__fadd_rn(ar, ac_), inter);
                    if (uni > 0.0f)
                        sup = __fdiv_rn(inter, uni) > 0.5f;
                }
            }
            unsigned m = __ballot_sync(0xFFFFFFFFu, sup);
            if (lane == 0) u.nm.mask[it][wrp] = m;
        }
        __syncthreads();
        if (tid < 128) {
            u32 o = 0;
#pragma unroll
            for (int w = 0; w < 16; w++) o |= u.nm.mask[tid][w];
            u.nm.rowAny[tid] = o;
        }
        __syncthreads();
        if (wrp == 0) {
            int kept = ct.kept;
            if (kept < MAXPC) {
                for (int i = r0; i < r0 + 128; i++) {
                    u32 word = __shfl_sync(0xFFFFFFFFu, kb, i >> 5);
                    if ((word >> (i & 31)) & 1u) {
                        if (lane == 0) keepIdx[kept] = i;
                        kept++;
                        if (kept == MAXPC) break;
                        if (u.nm.rowAny[i - r0])
                            kb &= ~u.nm.mask[i - r0][lane & 15];
                    }
                }
                if (lane == 0) ct.kept = kept;
            }
        }
        __syncthreads();
        if (ct.kept >= MAXPC) break;
    }
    if (wrp == 0 && lane < 16) keepbm[lane] = kb;
    __syncthreads();
    if (tid == 0) {
        ct.m = ct.kept;
        int kept = ct.kept;
        for (int i = 0; i < KC && kept < MAXPC; i++)
            if (!((keepbm[i >> 5] >> (i & 31)) & 1u)) keepIdx[kept++] = i;
        ct.kept = kept;
    }
    __syncthreads();

    if (tid < MAXPC) {
        int idx = keepIdx[tid];
        float sc = (tid < ct.m) ? u.nm.score[idx] : 0.0f;
        g_CS[task * MAXPC + tid] = sc;
        g_CB[task * MAXPC + tid] = u.nm.box[idx];
    }

    // ================== fused per-image combine (last CTA) ==================
    __threadfence();
    __syncthreads();
    if (tid == 0) {
        __threadfence();
        int prev = atomicAdd(&g_done[b], 1);
        isLast = (prev == N_CLS - 1) ? 1 : 0;
    }
    __syncthreads();
    if (!isLast) return;
    __threadfence();                          // acquire side

    // reset this image's shard counters for the next graph replay
    for (int t = tid; t < N_CLS * NSH; t += 512)
        g_cntp[(b * N_CLS * NSH + t) * PADU] = 0;

    const int TOTF = N_CLS * MAXPC;
    if (tid == 0) { ct.cnt = 0; ct.tcnt = 0; validCnt = 0; }
    for (int f = tid; f < TOTF; f += 512)
        u.Ssm[f] = __ldcg(&g_CS[b * TOTF + f]);
    __syncthreads();

    // ---------- exact top-100 SET selection (generic 3-level) ----------
    {
        const int shiftsS[3] = {21, 10, 0};
        const int widthsS[3] = {11, 11, 10};
        u32 prefix = 0; int ngt = 0;
        int state = 0;
        u32 TkeyBin = 0; int sh_fin = 0; int need = 0;
        for (int lvl = 0; lvl < 3 && state == 0; lvl++) {
            int nb = 1 << widthsS[lvl];
            for (int i = tid; i < nb; i += 512) hist[i] = 0;
            __syncthreads();
            int sh = shiftsS[lvl]; u32 bm = (u32)(nb - 1); int psh = sh + widthsS[lvl];
            for (int f = tid; f < TOTF; f += 512) {
                u32 hk = __float_as_uint(u.Ssm[f]);
                if (lvl == 0 || (hk >> psh) == prefix)
                    atomicAdd(&hist[(hk >> sh) & bm], 1);
            }
            __syncthreads();
            find_bin_parallel(hist, nb, MAXPC, ngt, &ct, warpTot);
            u32 Bb = ct.Bb; u32 bc = ct.bc; int ngt2 = ct.ngt;
            int nd = MAXPC - ngt2;
            if ((int)bc == nd) {
                state = 1; TkeyBin = (prefix << widthsS[lvl]) | Bb; sh_fin = sh; ngt = ngt2;
            } else if (bc <= 64) {
                state = 2; TkeyBin = (prefix << widthsS[lvl]) | Bb; sh_fin = sh;
                ngt = ngt2; need = nd;
            } else if (lvl < 2) {
                prefix = (prefix << widthsS[lvl]) | Bb; ngt = ngt2;
            } else {
                state = 3; TkeyBin = (prefix << widthsS[lvl]) | Bb; sh_fin = sh; ngt = ngt2;
            }
            __syncthreads();
        }

        u64 Tkey   = ((u64)TkeyBin) << sh_fin;
        u64 binTop = ((u64)TkeyBin + 1) << sh_fin;

        if (state == 1) {
            for (int f = tid; f < TOTF; f += 512) {
                u64 hk = __float_as_uint(u.Ssm[f]);
                if (hk >= Tkey) {
                    int p = atomicAdd(&ct.cnt, 1);
                    key512[p] = (hk << 32) | (0xFFFFFFFFu - (u32)f);
                }
            }
            __syncthreads();
        } else if (state == 2) {
            for (int f = tid; f < TOTF; f += 512) {
                u64 hk = __float_as_uint(u.Ssm[f]);
                if (hk >= binTop) {
                    int p = atomicAdd(&ct.cnt, 1);
                    key512[p] = (hk << 32) | (0xFFFFFFFFu - (u32)f);
                } else if (hk >= Tkey) {
                    int p = atomicAdd(&ct.tcnt, 1);
                    tiebuf[p] = (hk << 32) | (0xFFFFFFFFu - (u32)f);
                }
            }
            __syncthreads();
            if (wrp == 0) {
                int bcv = ct.tcnt;
                u64 a0 = (lane < bcv) ? tiebuf[lane] : 0ull;
                u64 a1 = (lane + 32 < bcv) ? tiebuf[lane + 32] : 0ull;
                warp64_sort_desc(a0, a1, lane);
                tiebuf[lane] = a0; tiebuf[lane + 32] = a1;
            }
            __syncthreads();
            if (tid < need) key512[ngt + tid] = tiebuf[tid];
            __syncthreads();
        } else {
            // bail: >64 identical keys; ascending-f scan is exact for ties
            for (int f = tid; f < TOTF; f += 512) {
                u64 hk = __float_as_uint(u.Ssm[f]);
                if (hk >= binTop) {
                    int p = atomicAdd(&ct.cnt, 1);
                    key512[p] = (hk << 32) | (0xFFFFFFFFu - (u32)f);
                }
            }
            __syncthreads();
            if (tid == 0) {
                int base = ct.cnt, got = 0, needB = MAXPC - base;
                for (int f = 0; f < TOTF && got < needB; f++) {
                    if (__float_as_uint(u.Ssm[f]) == TkeyBin) {
                        key512[base + got] = ((u64)TkeyBin << 32) | (0xFFFFFFFFu - (u32)f);
                        got++;
                    }
                }
            }
            __syncthreads();
        }
    }

    if (tid >= MAXPC) key512[tid] = 0ull;    // pad to 512
    __syncthreads();
    sort512_desc(key512);

    if (tid < MAXPC) {
        u64 e = key512[tid];
        float s = __uint_as_float((u32)(e >> 32));
        int f = (int)(0xFFFFFFFFu - (u32)e);
        bool valid = s > 0.0f;
        float vf = valid ? 1.0f : 0.0f;
        float4 bx;
        bx.x = __ldcg(&((const float*)g_CB)[(b * TOTF + f) * 4 + 0]);
        bx.y = __ldcg(&((const float*)g_CB)[(b * TOTF + f) * 4 + 1]);
        bx.z = __ldcg(&((const float*)g_CB)[(b * TOTF + f) * 4 + 2]);
        bx.w = __ldcg(&((const float*)g_CB)[(b * TOTF + f) * 4 + 3]);
        int o = (b * MAXPC + tid);
        out[o * 4 + 0] = __fmul_rn(fminf(fmaxf(bx.x, 0.0f), 1.0f), vf);
        out[o * 4 + 1] = __fmul_rn(fminf(fmaxf(bx.y, 0.0f), 1.0f), vf);
        out[o * 4 + 2] = __fmul_rn(fminf(fmaxf(bx.z, 0.0f), 1.0f), vf);
        out[o * 4 + 3] = __fmul_rn(fminf(fmaxf(bx.w, 0.0f), 1.0f), vf);
        out[B_IMG * MAXPC * 4 + o] = __fmul_rn(s, vf);
        out[B_IMG * MAXPC * 5 + o] = valid ? (float)(f / MAXPC) : 0.0f;
        if (valid) atomicAdd(&validCnt, 1);
    }
    __syncthreads();
    if (tid == 0) {
        out[B_IMG * MAXPC * 6 + b] = (float)validCnt;
        g_done[b] = 0;                       // reset for next graph replay
    }
}

// ------------------------------- launcher -----------------------------------
extern "C" void kernel_launch(void* const* d_in, const int* in_sizes, int n_in,
                              void* d_out, int out_size) {
    const float* pred = nullptr;
    for (int i = 0; i < n_in; i++)
        if (in_sizes[i] == B_IMG * N_ANCH * ROW_F)
            pred = (const float*)d_in[i];
    float* out = (float*)d_out;

    const int TOT = B_IMG * N_ANCH * 21;             // float4 count
    const int perBlock = 256 * CITER;
    collect_kernel<<<(TOT + perBlock - 1) / perBlock, 256>>>(pred);
    nms_kernel<<<B_IMG * N_CLS, 512>>>(pred, out);
}

// round 15
// speedup vs baseline: 1.5812x; 1.5812x over previous
#include <cuda_runtime.h>
#include <cstdint>
#include <math.h>

typedef unsigned long long u64;
typedef unsigned int u32;

#define B_IMG  4
#define N_ANCH 76725
#define N_CLS  80
#define ROW_F  84            // 80 classes + 4 box regressors
#define KC     512           // K_CAND
#define CAP    2048
#define MAXPC  100
#define THRESH 2.30f
#define CITER  4             // float4s per thread in collect
#define NSH    4             // counter shards per task
#define CAP_SH 512           // candidate slots per shard (4*512 = CAP)
#define PADU   32            // u32 per counter (128B line padding)

// ----------------------------- global scratch -------------------------------
__device__ u32    g_cntp[B_IMG * N_CLS * NSH * PADU];        // padded counters
__device__ u64    g_cand[(size_t)B_IMG * N_CLS * NSH * CAP_SH];
__device__ float  g_CS[B_IMG * N_CLS * MAXPC];
__device__ float4 g_CB[B_IMG * N_CLS * MAXPC];

// --------------------- XLA-exact sigmoid (logistic lowering) ----------------
__device__ __forceinline__ float xla_sigmoid(float x) {
    float hx = __fmul_rn(0.5f, x);
    float t;
    if (fabsf(hx) < 0.0004f) {
        t = hx;
    } else {
        float xc = fmaxf(fminf(hx, 7.99881172180175781f), -7.99881172180175781f);
        float x2 = __fmul_rn(xc, xc);
        float p = fmaf(x2, -2.76076847742355e-16f, 2.00018790482477e-13f);
        p = fmaf(x2, p, -8.60467152213735e-11f);
        p = fmaf(x2, p,  5.12229709037114e-08f);
        p = fmaf(x2, p,  1.48572235717979e-05f);
        p = fmaf(x2, p,  6.37261928875436e-04f);
        p = fmaf(x2, p,  4.89352455891786e-03f);
        p = __fmul_rn(xc, p);
        float q = fmaf(x2, 1.19825839466702e-06f, 1.18534705686654e-04f);
        q = fmaf(x2, q, 2.26843463243900e-03f);
        q = fmaf(x2, q, 4.89352518554385e-03f);
        t = __fdiv_rn(p, q);
    }
    return fmaf(0.5f, t, 0.5f);
}

// ----------------------------- control block --------------------------------
struct Ctl {
    int n, fb;
    u32 Bb, bc, Tb;
    int ngt;
    int tie, need, cnt, tcnt;
    int kept, m;
};

// ---- parallel "find rank-K bin from the top" over hist[nb] ------------------
__device__ __forceinline__ void find_bin_parallel(
    const u32* hist, int nb, int K, int ngt_in, Ctl* ct, u32* warpTot)
{
    const int tid = threadIdx.x;
    int g = nb >> 9;
    if (g < 1) g = 1;
    int hi = nb - 1 - tid * g;
    u32 tsum = 0;
#pragma unroll 4
    for (int e = 0; e < g; e++) {
        int bb = hi - e;
        if (bb >= 0) tsum += hist[bb];
    }
    u32 ln = tid & 31, wp = tid >> 5;
    u32 v = tsum;
#pragma unroll
    for (int off = 1; off < 32; off <<= 1) {
        u32 nv = __shfl_up_sync(0xFFFFFFFFu, v, off);
        if (ln >= off) v += nv;
    }
    if (ln == 31) warpTot[wp] = v;
    __syncthreads();
    if (wp == 0) {
        u32 w = (ln < 16) ? warpTot[ln] : 0;
#pragma unroll
        for (int off = 1; off < 16; off <<= 1) {
            u32 nv = __shfl_up_sync(0xFFFFFFFFu, w, off);
            if (ln >= off) w += nv;
        }
        if (ln < 16) warpTot[ln] = w;
    }
    __syncthreads();
    u32 excl = (v - tsum) + (wp ? warpTot[wp - 1] : 0u);
    u32 cum = (u32)ngt_in + excl;
#pragma unroll 4
    for (int e = 0; e < g; e++) {
        int bb = hi - e;
        if (bb < 0) break;
        u32 c = hist[bb];
        if ((int)cum < K && (int)(cum + c) >= K) {
            ct->Bb = (u32)bb; ct->bc = c; ct->ngt = (int)cum;
        }
        cum += c;
    }
    __syncthreads();
}

// ---- warp-0 bitonic sort of 64 u64 (2 per lane), descending, zero barriers -
__device__ __forceinline__ void warp64_sort_desc(u64& a0, u64& a1, int lane) {
#pragma unroll
    for (int k = 2; k <= 64; k <<= 1) {
        if (k == 64) { if (a0 < a1) { u64 t = a0; a0 = a1; a1 = t; } }
#pragma unroll
        for (int j = ((k >> 1) > 16 ? 16 : (k >> 1)); j >= 1; j >>= 1) {
            bool lower = (lane & j) == 0;
            bool d0 = (lane & k) == 0;
            bool d1 = ((lane + 32) & k) == 0;
            u64 p0 = __shfl_xor_sync(0xFFFFFFFFu, a0, j);
            u64 p1 = __shfl_xor_sync(0xFFFFFFFFu, a1, j);
            a0 = ((lower == d0) == (a0 >= p0)) ? a0 : p0;
            a1 = ((lower == d1) == (a1 >= p1)) ? a1 : p1;
        }
    }
}

// ---- hybrid shfl/smem bitonic sort of 512 u64, descending -------------------
__device__ __forceinline__ void sort512_desc(u64* arr) {
    const int tid = threadIdx.x;
    u64 v = arr[tid];
#pragma unroll
    for (int k = 2; k <= 512; k <<= 1) {
        bool desc = (tid & k) == 0;          // k=512 -> always true
        for (int j = k >> 1; j >= 32; j >>= 1) {
            __syncthreads();
            arr[tid] = v;
            __syncthreads();
            u64 pv = arr[tid ^ j];
            bool lower = (tid & j) == 0;
            v = ((lower == desc) == (v >= pv)) ? v : pv;
        }
#pragma unroll
        for (int j = ((k >> 1) > 16 ? 16 : (k >> 1)); j >= 1; j >>= 1) {
            u64 pv = __shfl_xor_sync(0xFFFFFFFFu, v, j);
            bool lower = (tid & j) == 0;
            v = ((lower == desc) == (v >= pv)) ? v : pv;
        }
    }
    __syncthreads();
    arr[tid] = v;
    __syncthreads();
}

// ------------- kernel 1: batched scan + fast-reject + candidate push ---------
__global__ void __launch_bounds__(256)
collect_kernel(const float* __restrict__ pred) {
    const int TOT = B_IMG * N_ANCH * 21;             // float4 count
    int base = blockIdx.x * (256 * CITER) + threadIdx.x;

    float4 v[CITER];
#pragma unroll
    for (int k = 0; k < CITER; k++) {
        int idx = base + k * 256;
        if (idx < TOT)
            v[k] = reinterpret_cast<const float4*>(pred)[idx];
    }

#pragma unroll
    for (int k = 0; k < CITER; k++) {
        int idx = base + k * 256;
        if (idx >= TOT) continue;
        float4 w = v[k];
        float m = fmaxf(fmaxf(w.x, w.y), fmaxf(w.z, w.w));
        if (m <= THRESH) continue;                    // fast reject (~95.8%)
        int b = idx / (N_ANCH * 21);
        int r = idx - b * (N_ANCH * 21);
        int a = r / 21;
        int q = r - a * 21;
        if (q == 20) continue;                        // box-regressor block
        int c0 = q * 4;
        int sh = a & (NSH - 1);
        u32 la = 0xFFFFFFFFu - (u32)a;
        float vals[4] = {w.x, w.y, w.z, w.w};
#pragma unroll
        for (int e = 0; e < 4; e++) {
            float x = vals[e];
            if (x > THRESH) {
                int slot = (b * N_CLS + c0 + e) * NSH + sh;
                u32 pos = atomicAdd(&g_cntp[slot * PADU], 1u);
                if (pos < CAP_SH) {
                    float s = xla_sigmoid(x);
                    g_cand[(size_t)slot * CAP_SH + pos] =
                        ((u64)__float_as_uint(s) << 32) | la;
                }
            }
        }
    }
}

// ------------------- kernel 2: per-(b,c) top-512 + NMS + top-100 ------------
struct NmsArrs {
    float4 box[KC];          // 8 KB
    float  area[KC];         // 2 KB
    float  score[KC];        // 2 KB
    u32    mask[128][16];    // 8 KB
    u32    rowAny[128];      // 0.5 KB
};
union BufU {
    u64     buf[CAP];        // 16 KB (candidate phase)
    NmsArrs nm;              // 20.5 KB (NMS phase)
};

__global__ void __launch_bounds__(512)
nms_kernel(const float* __restrict__ pred) {
    __shared__ BufU u;
    __shared__ u64 key512[KC];       // 4 KB
    __shared__ u32 hist[2048];       // 8 KB
    __shared__ u64 tiebuf[64];
    __shared__ u32 keepbm[16];
    __shared__ u32 validbm[16];
    __shared__ u32 warpTot[16];
    __shared__ int keepIdx[MAXPC];
    __shared__ int shCnt[NSH], shOff[NSH];
    __shared__ float awTab[45], ahTab[45];
    __shared__ int selDone;
    __shared__ Ctl ct;

    const int tid  = threadIdx.x;
    const int lane = tid & 31;
    const int wrp  = tid >> 5;
    const int task = blockIdx.x;
    const int b = task / N_CLS, c = task % N_CLS;

    // ---- anchor dims table: 45 (lvl3,k) pairs, same double math as numpy ----
    if (tid < 45) {
        int lvl3 = tid / 9, k = tid % 9;
        double side = (double)(1 << (lvl3 + 5));      // 2^(level+2), level=lvl3+3
        double area = side * side;
        const double ratios[3] = {0.5, 1.0, 2.0};
        const double scales[3] = {1.0, 1.2599210498948732, 1.5874010519681994};
        double r = ratios[k / 3], s = scales[k % 3];
        double ahd = sqrt(area / r);
        double awd = area / ahd;
        awTab[tid] = (float)(s * awd);
        ahTab[tid] = (float)(s * ahd);
    }

    if (tid < NSH)
        shCnt[tid] = (int)g_cntp[(task * NSH + tid) * PADU];
    __syncthreads();
    if (tid == 0) {
        int n0 = 0, bad = 0, off = 0;
        for (int s = 0; s < NSH; s++) {
            shOff[s] = off;
            int cs = shCnt[s];
            if (cs > CAP_SH) bad = 1;
            n0 += cs; off += cs;
        }
        ct.n = n0;
        ct.fb = (bad || n0 < KC || n0 > CAP) ? 1 : 0;
        ct.cnt = 0; ct.tcnt = 0; ct.kept = 0; ct.tie = 0;
        selDone = 0;
    }
    __syncthreads();
    const int fb = ct.fb;

    if (!fb) {
        // normal path: concatenate shard segments (order-free set)
#pragma unroll
        for (int s = 0; s < NSH; s++) {
            int cs = shCnt[s], off = shOff[s];
            const u64* src = g_cand + (size_t)(task * NSH + s) * CAP_SH;
            for (int i = tid; i < cs; i += 512)
                u.buf[off + i] = src[i];
        }
        __syncthreads();
    } else {
        // ---------- fallback: exact radix select on full column ----------
        const float* colb = pred + (size_t)b * N_ANCH * ROW_F + c;
        const int shifts[3] = {20, 9, 0};
        const int widths[3] = {11, 11, 9};
        u32 prefix = 0; int ngt = 0;
        int found = 0;
        for (int lvl = 0; lvl < 3 && !found; lvl++) {
            int nb = 1 << widths[lvl];
            for (int i = tid; i < nb; i += 512) hist[i] = 0;
            __syncthreads();
            int sh = shifts[lvl]; u32 bm = (u32)(nb - 1); int psh = sh + widths[lvl];
            for (int a = tid; a < N_ANCH; a += 512) {
                float s = xla_sigmoid(colb[(size_t)a * ROW_F]);
                u32 kb = __float_as_uint(s);
                if ((kb >> psh) == prefix) atomicAdd(&hist[(kb >> sh) & bm], 1);
            }
            __syncthreads();
            find_bin_parallel(hist, nb, KC, ngt, &ct, warpTot);
            u32 Bb = ct.Bb; int cum = ct.ngt; u32 bc = ct.bc;
            if (cum + (int)bc <= CAP) {
                if (tid == 0) ct.Tb = ((prefix << widths[lvl]) | Bb) << sh;
                found = 1;
            } else if (lvl == 2) {
                if (tid == 0) {
                    ct.tie = 1;
                    ct.Tb = (prefix << 9) | Bb;
                    ct.need = KC - cum;
                }
                found = 1;
            } else {
                prefix = (prefix << widths[lvl]) | Bb;
                ngt = cum;
            }
            __syncthreads();
        }
        int tie = ct.tie; u32 Tb = ct.Tb;
        for (int a = tid; a < N_ANCH; a += 512) {
            float s = xla_sigmoid(colb[(size_t)a * ROW_F]);
            u32 kb = __float_as_uint(s);
            bool take = tie ? (kb > Tb) : (kb >= Tb);
            if (take) {
                int pos = atomicAdd(&ct.cnt, 1);
                u.buf[pos] = ((u64)kb << 32) | (0xFFFFFFFFu - (u32)a);
            }
        }
        __syncthreads();
        if (tid == 0 && tie) {
            int base = ct.cnt, got = 0, need = ct.need;
            for (int a = 0; a < N_ANCH && got < need; a++) {
                float s = xla_sigmoid(colb[(size_t)a * ROW_F]);
                if (__float_as_uint(s) == Tb) {
                    u.buf[base + got] = ((u64)Tb << 32) | (0xFFFFFFFFu - (u32)a);
                    got++;
                }
            }
            ct.cnt = base + got;
        }
        __syncthreads();
        if (tid == 0) { ct.n = ct.cnt; ct.cnt = 0; ct.tcnt = 0; }
        __syncthreads();
    }

    // ---------- exact top-512 SET selection into key512 ----------
    const int n = ct.n;                      // in [512, 2048]

    if (!fb) {
        // FAST single-level: keys are sigmoid(x>2.3) in (0.908, 1.0), so
        // key>>23 == 0x7E constant => bin=(key>>12)&0x7FF is monotone.
        if (tid == 0) { ct.cnt = 0; ct.tcnt = 0; }
        for (int i = tid; i < 2048; i += 512) hist[i] = 0;
        __syncthreads();
        for (int i = tid; i < n; i += 512) {
            u32 hk = (u32)(u.buf[i] >> 32);
            atomicAdd(&hist[(hk >> 12) & 0x7FF], 1);
        }
        __syncthreads();
        find_bin_parallel(hist, 2048, KC, 0, &ct, warpTot);
        u32 Bb = ct.Bb, bc = ct.bc; int ngt = ct.ngt;
        int need = KC - ngt;
        u32 thr    = (0x3F000u | Bb) << 12;
        u32 thrTop = ((0x3F000u | Bb) + 1u) << 12;
        if ((int)bc == need) {
            for (int i = tid; i < n; i += 512) {
                u64 e = u.buf[i];
                if ((u32)(e >> 32) >= thr) {
                    int p = atomicAdd(&ct.cnt, 1);
                    key512[p] = e;
                }
            }
            if (tid == 0) selDone = 1;
            __syncthreads();
        } else if (bc <= 64) {
            for (int i = tid; i < n; i += 512) {
                u64 e = u.buf[i];
                u32 hk = (u32)(e >> 32);
                if (hk >= thrTop) {
                    int p = atomicAdd(&ct.cnt, 1);
                    key512[p] = e;
                } else if (hk >= thr) {
                    int p = atomicAdd(&ct.tcnt, 1);
                    tiebuf[p] = e;
                }
            }
            __syncthreads();
            if (wrp == 0) {
                int bcv = ct.tcnt;
                u64 a0 = (lane < bcv) ? tiebuf[lane] : 0ull;
                u64 a1 = (lane + 32 < bcv) ? tiebuf[lane + 32] : 0ull;
                warp64_sort_desc(a0, a1, lane);
                tiebuf[lane] = a0; tiebuf[lane + 32] = a1;
            }
            __syncthreads();
            if (tid < need) key512[ngt + tid] = tiebuf[tid];
            if (tid == 0) selDone = 1;
            __syncthreads();
        } else {
            __syncthreads();                 // fall through to generic
        }
    }

    if (!selDone) {
        // ---------- generic 3-level select (exact for arbitrary keys) -------
        if (tid == 0) { ct.cnt = 0; ct.tcnt = 0; }
        __syncthreads();
        const int shiftsS[3] = {21, 10, 0};
        const int widthsS[3] = {11, 11, 10};
        u32 prefix = 0; int ngt = 0;
        int state = 0;                       // 1=whole-bin, 2=tie-sort, 3=bail
        u32 TkeyBin = 0; int sh_fin = 0; int need = 0;
        for (int lvl = 0; lvl < 3 && state == 0; lvl++) {
            int nb = 1 << widthsS[lvl];
            for (int i = tid; i < nb; i += 512) hist[i] = 0;
            __syncthreads();
            int sh = shiftsS[lvl]; u32 bm = (u32)(nb - 1); int psh = sh + widthsS[lvl];
            for (int i = tid; i < n; i += 512) {
                u32 hk = (u32)(u.buf[i] >> 32);
                if (lvl == 0 || (hk >> psh) == prefix)
                    atomicAdd(&hist[(hk >> sh) & bm], 1);
            }
            __syncthreads();
            find_bin_parallel(hist, nb, KC, ngt, &ct, warpTot);
            u32 Bb = ct.Bb; u32 bc = ct.bc; int ngt2 = ct.ngt;
            int nd = KC - ngt2;
            if ((int)bc == nd) {
                state = 1; TkeyBin = (prefix << widthsS[lvl]) | Bb; sh_fin = sh; ngt = ngt2;
            } else if (bc <= 64) {
                state = 2; TkeyBin = (prefix << widthsS[lvl]) | Bb; sh_fin = sh;
                ngt = ngt2; need = nd;
            } else if (lvl < 2) {
                prefix = (prefix << widthsS[lvl]) | Bb; ngt = ngt2;
            } else {
                state = 3; TkeyBin = (prefix << widthsS[lvl]) | Bb; sh_fin = sh; ngt = ngt2;
            }
            __syncthreads();
        }

        u64 Tkey   = ((u64)TkeyBin) << sh_fin;
        u64 binTop = ((u64)TkeyBin + 1) << sh_fin;

        if (state == 1) {
            for (int i = tid; i < n; i += 512) {
                u64 e = u.buf[i];
                if ((u64)(u32)(e >> 32) >= Tkey) {
                    int p = atomicAdd(&ct.cnt, 1);
                    key512[p] = e;
                }
            }
            __syncthreads();
        } else if (state == 2) {
            for (int i = tid; i < n; i += 512) {
                u64 e = u.buf[i];
                u64 hk = (u32)(e >> 32);
                if (hk >= binTop) {
                    int p = atomicAdd(&ct.cnt, 1);
                    key512[p] = e;
                } else if (hk >= Tkey) {
                    int p = atomicAdd(&ct.tcnt, 1);
                    tiebuf[p] = e;
                }
            }
            __syncthreads();
            if (wrp == 0) {
                int bcv = ct.tcnt;
                u64 a0 = (lane < bcv) ? tiebuf[lane] : 0ull;
                u64 a1 = (lane + 32 < bcv) ? tiebuf[lane + 32] : 0ull;
                warp64_sort_desc(a0, a1, lane);
                tiebuf[lane] = a0; tiebuf[lane + 32] = a1;
            }
            __syncthreads();
            if (tid < need) key512[ngt + tid] = tiebuf[tid];
            __syncthreads();
        } else {
            // bail: >64 identical high-keys at exact-key level (never for real data)
            for (int i = tid; i < n; i += 512) {
                u64 e = u.buf[i];
                if ((u64)(u32)(e >> 32) >= binTop) {
                    int p = atomicAdd(&ct.cnt, 1);
                    key512[p] = e;
                }
            }
            __syncthreads();
            if (tid == 0) {
                int base = ct.cnt, got = 0, needB = KC - base;
                u64 last = 0xFFFFFFFFFFFFFFFFull;
                while (got < needB) {
                    u64 best = 0;
                    for (int i = 0; i < n; i++) {
                        u64 e = u.buf[i];
                        if ((u32)(e >> 32) == TkeyBin && e < last && e > best) best = e;
                    }
                    key512[base + got] = best; got++; last = best;
                }
            }
            __syncthreads();
        }
    }
    sort512_desc(key512);

    // ---------- decode boxes (u.buf dead -> u.nm live) ----------
    bool myValid;
    {
        u64 e = key512[tid];
        u32 lo = (u32)e;
        int a = (int)(0xFFFFFFFFu - lo);
        float s = __uint_as_float((u32)(e >> 32));
        float4 p = reinterpret_cast<const float4*>(pred)[(size_t)(b * N_ANCH + a) * 21 + 20];
        int base, fw, stride, lvl3;
        if      (a < 57600) { base = 0;     fw = 80; stride = 8;   lvl3 = 0; }
        else if (a < 72000) { base = 57600; fw = 40; stride = 16;  lvl3 = 1; }
        else if (a < 75600) { base = 72000; fw = 20; stride = 32;  lvl3 = 2; }
        else if (a < 76500) { base = 75600; fw = 10; stride = 64;  lvl3 = 3; }
        else                { base = 76500; fw = 5;  stride = 128; lvl3 = 4; }
        int local = a - base;
        int k    = local % 9;
        int cell = local / 9;
        int ix = cell % fw;
        int iy = cell / fw;
        float acx = __fmul_rn(__fadd_rn((float)ix, 0.5f), (float)stride);
        float acy = __fmul_rn(__fadd_rn((float)iy, 0.5f), (float)stride);
        float aw = awTab[lvl3 * 9 + k];
        float ah = ahTab[lvl3 * 9 + k];
        float cx = fmaf(__fmul_rn(p.x, 0.1f), aw, acx);
        float cy = fmaf(__fmul_rn(p.y, 0.1f), ah, acy);
        float w  = __fmul_rn(expf(__fmul_rn(p.z, 0.2f)), aw);
        float h  = __fmul_rn(expf(__fmul_rn(p.w, 0.2f)), ah);
        u.nm.box[tid]  = make_float4(cx, cy, w, h);
        u.nm.area[tid] = __fmul_rn(fmaxf(__fsub_rn(w, cx), 0.0f),
                                   fmaxf(__fsub_rn(h, cy), 0.0f));
        u.nm.score[tid] = s;
        myValid = (w > cx) && (h > cy);
        unsigned bal = __ballot_sync(0xFFFFFFFFu, s > 0.05f);
        if (lane == 0) keepbm[wrp] = bal;
        unsigned vb = __ballot_sync(0xFFFFFFFFu, myValid);
        if (lane == 0) validbm[wrp] = vb;
    }
    __syncthreads();

    // ---------- greedy NMS: mask chunks + warp-cooperative sweep ----------
    float4 bc_ = u.nm.box[tid];
    float  ac_ = u.nm.area[tid];
    u32 kb = 0;
    if (wrp == 0 && lane < 16) kb = keepbm[lane];

    for (int r0 = 0; r0 < KC; r0 += 128) {
        for (int it = 0; it < 128; it++) {
            int row = r0 + it;
            bool rowValid = (validbm[row >> 5] >> (row & 31)) & 1u;   // uniform
            if (!rowValid) {
                if (lane == 0) u.nm.mask[it][wrp] = 0;
                continue;
            }
            float4 br = u.nm.box[row];
            float  ar = u.nm.area[row];
            bool sup = false;
            if (myValid && tid > row) {
                float ih = fmaxf(__fsub_rn(fminf(br.z, bc_.z), fmaxf(br.x, bc_.x)), 0.0f);
                float iw = fmaxf(__fsub_rn(fminf(br.w, bc_.w), fmaxf(br.y, bc_.y)), 0.0f);
                float inter = __fmul_rn(ih, iw);
                if (inter > 0.0f) {
                    float uni = __fsub_rn(__fadd_rn(ar, ac_), inter);
                    if (uni > 0.0f)
                        sup = __fdiv_rn(inter, uni) > 0.5f;
                }
            }
            unsigned m = __ballot_sync(0xFFFFFFFFu, sup);
            if (lane == 0) u.nm.mask[it][wrp] = m;
        }
        __syncthreads();
        if (tid < 128) {
            u32 o = 0;
#pragma unroll
            for (int w = 0; w < 16; w++) o |= u.nm.mask[tid][w];
            u.nm.rowAny[tid] = o;
        }
        __syncthreads();
        if (wrp == 0) {
            int kept = ct.kept;
            if (kept < MAXPC) {
                for (int i = r0; i < r0 + 128; i++) {
                    u32 word = __shfl_sync(0xFFFFFFFFu, kb, i >> 5);
                    if ((word >> (i & 31)) & 1u) {
                        if (lane == 0) keepIdx[kept] = i;
                        kept++;
                        if (kept == MAXPC) break;
                        if (u.nm.rowAny[i - r0])
                            kb &= ~u.nm.mask[i - r0][lane & 15];
                    }
                }
                if (lane == 0) ct.kept = kept;
            }
        }
        __syncthreads();
        if (ct.kept >= MAXPC) break;
    }
    if (wrp == 0 && lane < 16) keepbm[lane] = kb;
    __syncthreads();
    if (tid == 0) {
        ct.m = ct.kept;
        int kept = ct.kept;
        for (int i = 0; i < KC && kept < MAXPC; i++)
            if (!((keepbm[i >> 5] >> (i & 31)) & 1u)) keepIdx[kept++] = i;
        ct.kept = kept;
    }
    __syncthreads();

    if (tid < MAXPC) {
        int idx = keepIdx[tid];
        float sc = (tid < ct.m) ? u.nm.score[idx] : 0.0f;
        g_CS[task * MAXPC + tid] = sc;
        g_CB[task * MAXPC + tid] = u.nm.box[idx];
    }
}

// ------------------- kernel 3: per-image combine (top-100 of 8000) ----------
__global__ void __launch_bounds__(512)
combine_kernel(float* __restrict__ out) {
    __shared__ float Ssm[N_CLS * MAXPC];   // 32 KB
    __shared__ u64 buf[KC];                // 4 KB
    __shared__ u32 hist[2048];             // 8 KB
    __shared__ u64 tiebuf[64];
    __shared__ u32 warpTot[16];
    __shared__ Ctl ct;
    __shared__ int validCnt;

    const int tid = threadIdx.x;
    const int lane = tid & 31;
    const int wrp  = tid >> 5;
    const int b = blockIdx.x;
    const float* S = g_CS + b * N_CLS * MAXPC;
    const int TOTF = N_CLS * MAXPC;

    // reset this image's padded shard counters for the next graph replay
    for (int t = tid; t < N_CLS * NSH; t += 512)
        g_cntp[(b * N_CLS * NSH + t) * PADU] = 0;

    if (tid == 0) { ct.cnt = 0; ct.tcnt = 0; validCnt = 0; }
    for (int f = tid; f < TOTF; f += 512) Ssm[f] = S[f];
    __syncthreads();

    // ---------- exact top-100 SET selection ----------
    {
        const int shiftsS[3] = {21, 10, 0};
        const int widthsS[3] = {11, 11, 10};
        u32 prefix = 0; int ngt = 0;
        int state = 0;
        u32 TkeyBin = 0; int sh_fin = 0; int need = 0;
        for (int lvl = 0; lvl < 3 && state == 0; lvl++) {
            int nb = 1 << widthsS[lvl];
            for (int i = tid; i < nb; i += 512) hist[i] = 0;
            __syncthreads();
            int sh = shiftsS[lvl]; u32 bm = (u32)(nb - 1); int psh = sh + widthsS[lvl];
            for (int f = tid; f < TOTF; f += 512) {
                u32 hk = __float_as_uint(Ssm[f]);
                if (lvl == 0 || (hk >> psh) == prefix)
                    atomicAdd(&hist[(hk >> sh) & bm], 1);
            }
            __syncthreads();
            find_bin_parallel(hist, nb, MAXPC, ngt, &ct, warpTot);
            u32 Bb = ct.Bb; u32 bc = ct.bc; int ngt2 = ct.ngt;
            int nd = MAXPC - ngt2;
            if ((int)bc == nd) {
                state = 1; TkeyBin = (prefix << widthsS[lvl]) | Bb; sh_fin = sh; ngt = ngt2;
            } else if (bc <= 64) {
                state = 2; TkeyBin = (prefix << widthsS[lvl]) | Bb; sh_fin = sh;
                ngt = ngt2; need = nd;
            } else if (lvl < 2) {
                prefix = (prefix << widthsS[lvl]) | Bb; ngt = ngt2;
            } else {
                state = 3; TkeyBin = (prefix << widthsS[lvl]) | Bb; sh_fin = sh; ngt = ngt2;
            }
            __syncthreads();
        }

        u64 Tkey   = ((u64)TkeyBin) << sh_fin;
        u64 binTop = ((u64)TkeyBin + 1) << sh_fin;

        if (state == 1) {
            for (int f = tid; f < TOTF; f += 512) {
                u64 hk = __float_as_uint(Ssm[f]);
                if (hk >= Tkey) {
                    int p = atomicAdd(&ct.cnt, 1);
                    buf[p] = (hk << 32) | (0xFFFFFFFFu - (u32)f);
                }
            }
            __syncthreads();
        } else if (state == 2) {
            for (int f = tid; f < TOTF; f += 512) {
                u64 hk = __float_as_uint(Ssm[f]);
                if (hk >= binTop) {
                    int p = atomicAdd(&ct.cnt, 1);
                    buf[p] = (hk << 32) | (0xFFFFFFFFu - (u32)f);
                } else if (hk >= Tkey) {
                    int p = atomicAdd(&ct.tcnt, 1);
                    tiebuf[p] = (hk << 32) | (0xFFFFFFFFu - (u32)f);
                }
            }
            __syncthreads();
            if (wrp == 0) {
                int bcv = ct.tcnt;
                u64 a0 = (lane < bcv) ? tiebuf[lane] : 0ull;
                u64 a1 = (lane + 32 < bcv) ? tiebuf[lane + 32] : 0ull;
                warp64_sort_desc(a0, a1, lane);
                tiebuf[lane] = a0; tiebuf[lane + 32] = a1;
            }
            __syncthreads();
            if (tid < need) buf[ngt + tid] = tiebuf[tid];
            __syncthreads();
        } else {
            // bail: >64 identical keys; ascending-f scan is exact for ties
            for (int f = tid; f < TOTF; f += 512) {
                u64 hk = __float_as_uint(Ssm[f]);
                if (hk >= binTop) {
                    int p = atomicAdd(&ct.cnt, 1);
                    buf[p] = (hk << 32) | (0xFFFFFFFFu - (u32)f);
                }
            }
            __syncthreads();
            if (tid == 0) {
                int base = ct.cnt, got = 0, needB = MAXPC - base;
                for (int f = 0; f < TOTF && got < needB; f++) {
                    if (__float_as_uint(Ssm[f]) == TkeyBin) {
                        buf[base + got] = ((u64)TkeyBin << 32) | (0xFFFFFFFFu - (u32)f);
                        got++;
                    }
                }
            }
            __syncthreads();
        }
    }

    if (tid >= MAXPC) buf[tid] = 0ull;     // pad to 512
    __syncthreads();
    sort512_desc(buf);

    if (tid < MAXPC) {
        u64 e = buf[tid];
        float s = __uint_as_float((u32)(e >> 32));
        int f = (int)(0xFFFFFFFFu - (u32)e);
        bool valid = s > 0.0f;
        float vf = valid ? 1.0f : 0.0f;
        float4 bx = g_CB[b * TOTF + f];
        int o = (b * MAXPC + tid);
        out[o * 4 + 0] = __fmul_rn(fminf(fmaxf(bx.x, 0.0f), 1.0f), vf);
        out[o * 4 + 1] = __fmul_rn(fminf(fmaxf(bx.y, 0.0f), 1.0f), vf);
        out[o * 4 + 2] = __fmul_rn(fminf(fmaxf(bx.z, 0.0f), 1.0f), vf);
        out[o * 4 + 3] = __fmul_rn(fminf(fmaxf(bx.w, 0.0f), 1.0f), vf);
        out[B_IMG * MAXPC * 4 + o] = __fmul_rn(s, vf);
        out[B_IMG * MAXPC * 5 + o] = valid ? (float)(f / MAXPC) : 0.0f;
        if (valid) atomicAdd(&validCnt, 1);
    }
    __syncthreads();
    if (tid == 0) out[B_IMG * MAXPC * 6 + b] = (float)validCnt;
}

// ------------------------------- launcher -----------------------------------
extern "C" void kernel_launch(void* const* d_in, const int* in_sizes, int n_in,
                              void* d_out, int out_size) {
    const float* pred = nullptr;
    for (int i = 0; i < n_in; i++)
        if (in_sizes[i] == B_IMG * N_ANCH * ROW_F)
            pred = (const float*)d_in[i];
    float* out = (float*)d_out;

    const int TOT = B_IMG * N_ANCH * 21;             // float4 count
    const int perBlock = 256 * CITER;
    collect_kernel<<<(TOT + perBlock - 1) / perBlock, 256>>>(pred);
    nms_kernel<<<B_IMG * N_CLS, 512>>>(pred);
    combine_kernel<<<B_IMG, 512>>>(out);
}